// round 8
// baseline (speedup 1.0000x reference)
#include <cuda_runtime.h>
#include <math.h>

// Shapes fixed: x, target = [B=8, C=256, H=128, W=128] fp32.
#define B_DIM   8
#define C_DIM   256
#define HW_DIM  (128 * 128)                 // 16384 floats per (b,c) slab
#define N_PER_C ((float)(B_DIM * HW_DIM))   // 131072 elements per channel
#define SLABS   (B_DIM * C_DIM)             // 2048 flat slabs, slab s = b*256 + c
#define THREADS 256
#define P2_ITER (HW_DIM / (THREADS * 4))    // 16 ulonglong2 loads (4 floats) per thread/tensor

// Per-slab partial sums, moment-major. Fully rewritten every launch.
__device__ float g_part[10][SLABS];
__device__ unsigned int g_done;  // zero at load; last CTA resets it each launch

typedef unsigned long long ull;

// Blackwell packed f32x2 ops (FMA pipe, 2 floats per instruction; PTX-only).
__device__ __forceinline__ ull mul2(ull a, ull b) {
    ull r; asm("mul.rn.f32x2 %0, %1, %2;" : "=l"(r) : "l"(a), "l"(b)); return r;
}
__device__ __forceinline__ ull add2(ull a, ull b) {
    ull r; asm("add.rn.f32x2 %0, %1, %2;" : "=l"(r) : "l"(a), "l"(b)); return r;
}
__device__ __forceinline__ ull fma2(ull a, ull b, ull c) {
    ull r; asm("fma.rn.f32x2 %0, %1, %2, %3;" : "=l"(r) : "l"(a), "l"(b), "l"(c)); return r;
}
__device__ __forceinline__ float unpack_sum(ull p) {
    unsigned int lo = (unsigned int)p, hi = (unsigned int)(p >> 32);
    return __uint_as_float(lo) + __uint_as_float(hi);
}

__device__ __forceinline__ float warp_red(float v) {
#pragma unroll
    for (int o = 16; o; o >>= 1) v += __shfl_xor_sync(0xffffffffu, v, o);
    return v;
}

// minBlocksPerMultiprocessor=6 caps regs at 42: the hot loop fits (~38);
// the once-per-launch finalize tail may spill to local — harmless.
__global__ __launch_bounds__(THREADS, 6) void style_loss_kernel(
    const float* __restrict__ x, const float* __restrict__ y,
    float* __restrict__ out) {
    const int s = blockIdx.x;                       // contiguous 64KB slab
    const size_t base = (size_t)s * HW_DIM;
    const ulonglong2* __restrict__ x2 = (const ulonglong2*)(x + base);
    const ulonglong2* __restrict__ y2 = (const ulonglong2*)(y + base);
    const int tid = threadIdx.x;

    // f32x2 accumulators: each holds 2 reduction lanes.
    ull sx1 = 0, sx2 = 0, sx3 = 0, sx4 = 0, sx5 = 0;
    ull sy1 = 0, sy2 = 0, sy3 = 0, sy4 = 0, sy5 = 0;

#pragma unroll 4
    for (int i = 0; i < P2_ITER; i++) {
        ulonglong2 vx = __ldcs(&x2[tid + i * THREADS]);  // 4 floats, streamed
        ulonglong2 vy = __ldcs(&y2[tid + i * THREADS]);
#pragma unroll
        for (int l = 0; l < 2; l++) {
            ull p = (l == 0) ? vx.x : vx.y;
            ull p2 = mul2(p, p);
            ull p3 = mul2(p2, p);
            sx1 = add2(sx1, p);
            sx2 = add2(sx2, p2);
            sx3 = add2(sx3, p3);
            sx4 = fma2(p2, p2, sx4);
            sx5 = fma2(p3, p2, sx5);
            ull q = (l == 0) ? vy.x : vy.y;
            ull q2 = mul2(q, q);
            ull q3 = mul2(q2, q);
            sy1 = add2(sy1, q);
            sy2 = add2(sy2, q2);
            sy3 = add2(sy3, q3);
            sy4 = fma2(q2, q2, sy4);
            sy5 = fma2(q3, q2, sy5);
        }
    }

    // Collapse packed lanes, then fp32 warp tree-reduce.
    float a1 = warp_red(unpack_sum(sx1)), a2 = warp_red(unpack_sum(sx2));
    float a3 = warp_red(unpack_sum(sx3)), a4 = warp_red(unpack_sum(sx4));
    float a5 = warp_red(unpack_sum(sx5));
    float b1 = warp_red(unpack_sum(sy1)), b2 = warp_red(unpack_sum(sy2));
    float b3 = warp_red(unpack_sum(sy3)), b4 = warp_red(unpack_sum(sy4));
    float b5 = warp_red(unpack_sum(sy5));

    __shared__ float sh[THREADS / 32][10];
    const int lane = tid & 31, wid = tid >> 5;
    if (lane == 0) {
        sh[wid][0] = a1; sh[wid][1] = a2; sh[wid][2] = a3; sh[wid][3] = a4; sh[wid][4] = a5;
        sh[wid][5] = b1; sh[wid][6] = b2; sh[wid][7] = b3; sh[wid][8] = b4; sh[wid][9] = b5;
    }
    __syncthreads();
    if (tid < 10) {
        float a = 0.f;
#pragma unroll
        for (int w = 0; w < THREADS / 32; w++) a += sh[w][tid];
        g_part[tid][s] = a;
    }

    // ---- last-block finalize (acq_rel atomic; no __threadfence / CCTL.IVALL) ----
    __shared__ bool s_last;
    if (tid == 0) {
        unsigned int n;
        asm volatile("atom.add.acq_rel.gpu.global.u32 %0, [%1], 1;"
                     : "=r"(n) : "l"(&g_done) : "memory");
        s_last = (n == (unsigned int)(SLABS - 1));
    }
    __syncthreads();  // propagates tid0's acquire to the whole CTA
    if (!s_last) return;

    // Last CTA: read partials via L2 (__ldcg bypasses possibly-stale L1 lines).
    const int c = tid;  // one thread per channel
    float sm[10];
#pragma unroll
    for (int j = 0; j < 10; j++) sm[j] = 0.f;
#pragma unroll
    for (int b = 0; b < B_DIM; b++) {
#pragma unroll
        for (int j = 0; j < 10; j++)
            sm[j] += __ldcg(&g_part[j][b * C_DIM + c]);  // coalesced, L2-hot
    }
    const float inv = 1.0f / N_PER_C;
    float mux = sm[0] * inv, r2x = sm[1] * inv, r3x = sm[2] * inv, r4x = sm[3] * inv, r5x = sm[4] * inv;
    float muy = sm[5] * inv, r2y = sm[6] * inv, r3y = sm[7] * inv, r4y = sm[8] * inv, r5y = sm[9] * inv;

    float mux2 = mux * mux, muy2 = muy * muy;
    // exact binomial recovery of centered moments from raw moments
    float m2x = r2x - mux2;
    float m3x = r3x - 3.f * mux * r2x + 2.f * mux2 * mux;
    float m4x = r4x - 4.f * mux * r3x + 6.f * mux2 * r2x - 3.f * mux2 * mux2;
    float m5x = r5x - 5.f * mux * r4x + 10.f * mux2 * r3x - 10.f * mux2 * mux * r2x
              + 4.f * mux2 * mux2 * mux;
    float m2y = r2y - muy2;
    float m3y = r3y - 3.f * muy * r2y + 2.f * muy2 * muy;
    float m4y = r4y - 4.f * muy * r3y + 6.f * muy2 * r2y - 3.f * muy2 * muy2;
    float m5y = r5y - 5.f * muy * r4y + 10.f * muy2 * r3y - 10.f * muy2 * muy * r2y
              + 4.f * muy2 * muy2 * muy;

    float d1 = mux - muy, d2 = m2x - m2y, d3 = m3x - m3y, d4 = m4x - m4y, d5 = m5x - m5y;
    float q[5] = { d1 * d1, d2 * d2, d3 * d3, d4 * d4, d5 * d5 };

#pragma unroll
    for (int k = 0; k < 5; k++) {
#pragma unroll
        for (int o = 16; o; o >>= 1) q[k] += __shfl_xor_sync(0xffffffffu, q[k], o);
    }
    __shared__ float shq[8][5];
    if (lane == 0) {
#pragma unroll
        for (int k = 0; k < 5; k++) shq[wid][k] = q[k];
    }
    __syncthreads();
    if (tid == 0) {
        float tot[5] = {0, 0, 0, 0, 0};
#pragma unroll
        for (int w = 0; w < 8; w++)
#pragma unroll
            for (int k = 0; k < 5; k++) tot[k] += shq[w][k];
        out[0] = sqrtf(tot[0]) + sqrtf(tot[1]) + sqrtf(tot[2]) + sqrtf(tot[3]) + sqrtf(tot[4]);
        g_done = 0u;  // reset for next (graph-replayed) launch
    }
}

extern "C" void kernel_launch(void* const* d_in, const int* in_sizes, int n_in,
                              void* d_out, int out_size) {
    const float* x = (const float*)d_in[0];
    const float* t = (const float*)d_in[1];
    style_loss_kernel<<<SLABS, THREADS>>>(x, t, (float*)d_out);
}

// round 9
// speedup vs baseline: 1.0240x; 1.0240x over previous
#include <cuda_runtime.h>
#include <math.h>

// Shapes fixed: x, target = [B=8, C=256, H=128, W=128] fp32.
#define B_DIM   8
#define C_DIM   256
#define HW_DIM  (128 * 128)                 // 16384 floats per (b,c) slab
#define N_PER_C ((float)(B_DIM * HW_DIM))   // 131072 elements per channel
#define SLABS   (B_DIM * C_DIM)             // 2048 flat slabs, slab s = b*256 + c
#define THREADS 256
#define P2_ITER (HW_DIM / (THREADS * 4))    // 16 ulonglong2 loads (4 floats) per thread/tensor

// Per-slab partial sums, moment-major for coalesced finalize reads.
__device__ float g_part[10][SLABS];

typedef unsigned long long ull;

// Blackwell packed f32x2 ops (FMA pipe, 2 floats per instruction; PTX-only).
__device__ __forceinline__ ull mul2(ull a, ull b) {
    ull r; asm("mul.rn.f32x2 %0, %1, %2;" : "=l"(r) : "l"(a), "l"(b)); return r;
}
__device__ __forceinline__ ull add2(ull a, ull b) {
    ull r; asm("add.rn.f32x2 %0, %1, %2;" : "=l"(r) : "l"(a), "l"(b)); return r;
}
__device__ __forceinline__ ull fma2(ull a, ull b, ull c) {
    ull r; asm("fma.rn.f32x2 %0, %1, %2, %3;" : "=l"(r) : "l"(a), "l"(b), "l"(c)); return r;
}
__device__ __forceinline__ float unpack_sum(ull p) {
    unsigned int lo = (unsigned int)p, hi = (unsigned int)(p >> 32);
    return __uint_as_float(lo) + __uint_as_float(hi);
}

__device__ __forceinline__ float warp_red(float v) {
#pragma unroll
    for (int o = 16; o; o >>= 1) v += __shfl_xor_sync(0xffffffffu, v, o);
    return v;
}

// EXACT R6 hot kernel (fastest measured: 40.9us, 38 regs, DRAM 82%) plus a
// trailing PDL trigger (no effect on the loop; fires after g_part stores).
__global__ __launch_bounds__(THREADS) void moments_kernel(
    const float* __restrict__ x, const float* __restrict__ y) {
    const int s = blockIdx.x;                       // contiguous 64KB slab
    const size_t base = (size_t)s * HW_DIM;
    const ulonglong2* __restrict__ x2 = (const ulonglong2*)(x + base);
    const ulonglong2* __restrict__ y2 = (const ulonglong2*)(y + base);
    const int tid = threadIdx.x;

    // f32x2 accumulators: each holds 2 reduction lanes.
    ull sx1 = 0, sx2 = 0, sx3 = 0, sx4 = 0, sx5 = 0;
    ull sy1 = 0, sy2 = 0, sy3 = 0, sy4 = 0, sy5 = 0;

#pragma unroll 4
    for (int i = 0; i < P2_ITER; i++) {
        ulonglong2 vx = __ldcs(&x2[tid + i * THREADS]);  // 4 floats, streamed
        ulonglong2 vy = __ldcs(&y2[tid + i * THREADS]);
#pragma unroll
        for (int l = 0; l < 2; l++) {
            ull p = (l == 0) ? vx.x : vx.y;
            ull p2 = mul2(p, p);
            ull p3 = mul2(p2, p);
            sx1 = add2(sx1, p);
            sx2 = add2(sx2, p2);
            sx3 = add2(sx3, p3);
            sx4 = fma2(p2, p2, sx4);
            sx5 = fma2(p3, p2, sx5);
            ull q = (l == 0) ? vy.x : vy.y;
            ull q2 = mul2(q, q);
            ull q3 = mul2(q2, q);
            sy1 = add2(sy1, q);
            sy2 = add2(sy2, q2);
            sy3 = add2(sy3, q3);
            sy4 = fma2(q2, q2, sy4);
            sy5 = fma2(q3, q2, sy5);
        }
    }

    // Collapse packed lanes, then fp32 warp tree-reduce.
    float a1 = warp_red(unpack_sum(sx1)), a2 = warp_red(unpack_sum(sx2));
    float a3 = warp_red(unpack_sum(sx3)), a4 = warp_red(unpack_sum(sx4));
    float a5 = warp_red(unpack_sum(sx5));
    float b1 = warp_red(unpack_sum(sy1)), b2 = warp_red(unpack_sum(sy2));
    float b3 = warp_red(unpack_sum(sy3)), b4 = warp_red(unpack_sum(sy4));
    float b5 = warp_red(unpack_sum(sy5));

    __shared__ float sh[THREADS / 32][10];
    const int lane = tid & 31, wid = tid >> 5;
    if (lane == 0) {
        sh[wid][0] = a1; sh[wid][1] = a2; sh[wid][2] = a3; sh[wid][3] = a4; sh[wid][4] = a5;
        sh[wid][5] = b1; sh[wid][6] = b2; sh[wid][7] = b3; sh[wid][8] = b4; sh[wid][9] = b5;
    }
    __syncthreads();
    if (tid < 10) {
        float a = 0.f;
#pragma unroll
        for (int w = 0; w < THREADS / 32; w++) a += sh[w][tid];
        g_part[tid][s] = a;
    }
    // PDL: writes above are program-order-before the trigger -> visible to the
    // dependent kernel after its cudaGridDependencySynchronize().
    cudaTriggerProgrammaticLaunchCompletion();
}

// All-fp32 finalize, launched with PDL so its prologue overlaps the moments
// tail; only ~1-2us of real work stays exposed.
__global__ __launch_bounds__(C_DIM) void finalize_kernel(float* __restrict__ out) {
    cudaGridDependencySynchronize();  // wait for moments grid + memory visibility

    const int c = threadIdx.x;  // one thread per channel; lanes consecutive in c
    float s[10];
#pragma unroll
    for (int j = 0; j < 10; j++) s[j] = 0.f;
#pragma unroll
    for (int b = 0; b < B_DIM; b++) {
#pragma unroll
        for (int j = 0; j < 10; j++)
            s[j] += __ldcg(&g_part[j][b * C_DIM + c]);  // coalesced, L2-hot
    }
    const float inv = 1.0f / N_PER_C;
    float mux = s[0] * inv, r2x = s[1] * inv, r3x = s[2] * inv, r4x = s[3] * inv, r5x = s[4] * inv;
    float muy = s[5] * inv, r2y = s[6] * inv, r3y = s[7] * inv, r4y = s[8] * inv, r5y = s[9] * inv;

    float mux2 = mux * mux, muy2 = muy * muy;
    // exact binomial recovery of centered moments from raw moments
    float m2x = r2x - mux2;
    float m3x = r3x - 3.f * mux * r2x + 2.f * mux2 * mux;
    float m4x = r4x - 4.f * mux * r3x + 6.f * mux2 * r2x - 3.f * mux2 * mux2;
    float m5x = r5x - 5.f * mux * r4x + 10.f * mux2 * r3x - 10.f * mux2 * mux * r2x
              + 4.f * mux2 * mux2 * mux;
    float m2y = r2y - muy2;
    float m3y = r3y - 3.f * muy * r2y + 2.f * muy2 * muy;
    float m4y = r4y - 4.f * muy * r3y + 6.f * muy2 * r2y - 3.f * muy2 * muy2;
    float m5y = r5y - 5.f * muy * r4y + 10.f * muy2 * r3y - 10.f * muy2 * muy * r2y
              + 4.f * muy2 * muy2 * muy;

    float d1 = mux - muy, d2 = m2x - m2y, d3 = m3x - m3y, d4 = m4x - m4y, d5 = m5x - m5y;
    float q[5] = { d1 * d1, d2 * d2, d3 * d3, d4 * d4, d5 * d5 };

#pragma unroll
    for (int k = 0; k < 5; k++) {
#pragma unroll
        for (int o = 16; o; o >>= 1) q[k] += __shfl_xor_sync(0xffffffffu, q[k], o);
    }
    __shared__ float shq[8][5];
    const int lane = c & 31, wid = c >> 5;
    if (lane == 0) {
#pragma unroll
        for (int k = 0; k < 5; k++) shq[wid][k] = q[k];
    }
    __syncthreads();
    if (c == 0) {
        float tot[5] = {0, 0, 0, 0, 0};
#pragma unroll
        for (int w = 0; w < 8; w++)
#pragma unroll
            for (int k = 0; k < 5; k++) tot[k] += shq[w][k];
        out[0] = sqrtf(tot[0]) + sqrtf(tot[1]) + sqrtf(tot[2]) + sqrtf(tot[3]) + sqrtf(tot[4]);
    }
}

extern "C" void kernel_launch(void* const* d_in, const int* in_sizes, int n_in,
                              void* d_out, int out_size) {
    const float* x = (const float*)d_in[0];
    const float* t = (const float*)d_in[1];

    moments_kernel<<<SLABS, THREADS>>>(x, t);

    // Dependent launch with Programmatic Stream Serialization: the finalize's
    // launch/prologue overlaps the moments grid; ordering is enforced by
    // cudaGridDependencySynchronize() inside the kernel.
    cudaLaunchConfig_t cfg = {};
    cfg.gridDim = dim3(1, 1, 1);
    cfg.blockDim = dim3(C_DIM, 1, 1);
    cfg.dynamicSmemBytes = 0;
    cudaLaunchAttribute attr[1];
    attr[0].id = cudaLaunchAttributeProgrammaticStreamSerialization;
    attr[0].val.programmaticStreamSerializationAllowed = 1;
    cfg.attrs = attr;
    cfg.numAttrs = 1;
    cudaLaunchKernelEx(&cfg, finalize_kernel, (float*)d_out);
}

// round 10
// speedup vs baseline: 1.0686x; 1.0436x over previous
#include <cuda_runtime.h>
#include <math.h>

// Shapes fixed: x, target = [B=8, C=256, H=128, W=128] fp32.
#define B_DIM   8
#define C_DIM   256
#define HW_DIM  (128 * 128)                 // 16384 floats per (b,c) slab
#define N_PER_C ((float)(B_DIM * HW_DIM))   // 131072 elements per channel
#define SLABS   (B_DIM * C_DIM)             // 2048 flat slabs, slab s = b*256 + c
#define THREADS 256
#define P2_ITER (HW_DIM / (THREADS * 4))    // 16 ulonglong2 loads (4 floats) per thread/tensor

// Per-slab partial sums, moment-major. Fully rewritten every launch.
__device__ float g_part[10][SLABS];
__device__ unsigned int g_done;  // zero at load; last CTA resets it each launch

typedef unsigned long long ull;

// Blackwell packed f32x2 ops (FMA pipe, 2 floats per instruction; PTX-only).
__device__ __forceinline__ ull mul2(ull a, ull b) {
    ull r; asm("mul.rn.f32x2 %0, %1, %2;" : "=l"(r) : "l"(a), "l"(b)); return r;
}
__device__ __forceinline__ ull add2(ull a, ull b) {
    ull r; asm("add.rn.f32x2 %0, %1, %2;" : "=l"(r) : "l"(a), "l"(b)); return r;
}
__device__ __forceinline__ ull fma2(ull a, ull b, ull c) {
    ull r; asm("fma.rn.f32x2 %0, %1, %2, %3;" : "=l"(r) : "l"(a), "l"(b), "l"(c)); return r;
}
__device__ __forceinline__ float unpack_sum(ull p) {
    unsigned int lo = (unsigned int)p, hi = (unsigned int)(p >> 32);
    return __uint_as_float(lo) + __uint_as_float(hi);
}

__device__ __forceinline__ float warp_red(float v) {
#pragma unroll
    for (int o = 16; o; o >>= 1) v += __shfl_xor_sync(0xffffffffu, v, o);
    return v;
}

__global__ __launch_bounds__(THREADS) void style_loss_kernel(
    const float* __restrict__ x, const float* __restrict__ y,
    float* __restrict__ out) {
    const int s = blockIdx.x;                       // contiguous 64KB slab
    const size_t base = (size_t)s * HW_DIM;
    const ulonglong2* __restrict__ x2 = (const ulonglong2*)(x + base);
    const ulonglong2* __restrict__ y2 = (const ulonglong2*)(y + base);
    const int tid = threadIdx.x;

    // ===== hot loop: byte-identical to R6 (40.9us, DRAM 82%) =====
    ull sx1 = 0, sx2 = 0, sx3 = 0, sx4 = 0, sx5 = 0;
    ull sy1 = 0, sy2 = 0, sy3 = 0, sy4 = 0, sy5 = 0;

#pragma unroll 4
    for (int i = 0; i < P2_ITER; i++) {
        ulonglong2 vx = __ldcs(&x2[tid + i * THREADS]);  // 4 floats, streamed
        ulonglong2 vy = __ldcs(&y2[tid + i * THREADS]);
#pragma unroll
        for (int l = 0; l < 2; l++) {
            ull p = (l == 0) ? vx.x : vx.y;
            ull p2 = mul2(p, p);
            ull p3 = mul2(p2, p);
            sx1 = add2(sx1, p);
            sx2 = add2(sx2, p2);
            sx3 = add2(sx3, p3);
            sx4 = fma2(p2, p2, sx4);
            sx5 = fma2(p3, p2, sx5);
            ull q = (l == 0) ? vy.x : vy.y;
            ull q2 = mul2(q, q);
            ull q3 = mul2(q2, q);
            sy1 = add2(sy1, q);
            sy2 = add2(sy2, q2);
            sy3 = add2(sy3, q3);
            sy4 = fma2(q2, q2, sy4);
            sy5 = fma2(q3, q2, sy5);
        }
    }

    float a1 = warp_red(unpack_sum(sx1)), a2 = warp_red(unpack_sum(sx2));
    float a3 = warp_red(unpack_sum(sx3)), a4 = warp_red(unpack_sum(sx4));
    float a5 = warp_red(unpack_sum(sx5));
    float b1 = warp_red(unpack_sum(sy1)), b2 = warp_red(unpack_sum(sy2));
    float b3 = warp_red(unpack_sum(sy3)), b4 = warp_red(unpack_sum(sy4));
    float b5 = warp_red(unpack_sum(sy5));

    __shared__ float sh[THREADS / 32][10];
    const int lane = tid & 31, wid = tid >> 5;
    if (lane == 0) {
        sh[wid][0] = a1; sh[wid][1] = a2; sh[wid][2] = a3; sh[wid][3] = a4; sh[wid][4] = a5;
        sh[wid][5] = b1; sh[wid][6] = b2; sh[wid][7] = b3; sh[wid][8] = b4; sh[wid][9] = b5;
    }
    __syncthreads();
    if (tid < 10) {
        float a = 0.f;
#pragma unroll
        for (int w = 0; w < THREADS / 32; w++) a += sh[w][tid];
        g_part[tid][s] = a;
    }

    // ===== last-block finalize: acq_rel atomic (no fence), register-LIGHT tail =====
    __shared__ bool s_last;
    if (tid == 0) {
        unsigned int n;
        asm volatile("atom.add.acq_rel.gpu.global.u32 %0, [%1], 1;"
                     : "=r"(n) : "l"(&g_done) : "memory");
        s_last = (n == (unsigned int)(SLABS - 1));
    }
    __syncthreads();
    if (!s_last) return;

    // Tail runs once per launch. All bulk state lives in SHARED (S[10][256]),
    // formula staged through S with <=9 live floats, j-loop forced sequential —
    // keeps peak register demand below the hot loop's so ptxas stays at ~38
    // regs and occupancy is unharmed (the R7 failure mode).
    __shared__ float S[10][C_DIM];
    const int c = tid;  // one thread per channel
#pragma unroll 1
    for (int j = 0; j < 10; j++) {
        float a = 0.f;
#pragma unroll
        for (int b = 0; b < B_DIM; b++)
            a += __ldcg(&g_part[j][b * C_DIM + c]);  // coalesced, L2-hot
        S[j][c] = a;
    }
    const float inv = 1.0f / N_PER_C;
    {   // x-side centered moments, written back into S[0..4]
        float mu = S[0][c] * inv;
        float r2 = S[1][c] * inv, r3 = S[2][c] * inv, r4 = S[3][c] * inv, r5 = S[4][c] * inv;
        float mu2 = mu * mu;
        S[0][c] = mu;
        S[1][c] = r2 - mu2;
        S[2][c] = r3 - 3.f * mu * r2 + 2.f * mu2 * mu;
        S[3][c] = r4 - 4.f * mu * r3 + 6.f * mu2 * r2 - 3.f * mu2 * mu2;
        S[4][c] = r5 - 5.f * mu * r4 + 10.f * mu2 * r3 - 10.f * mu2 * mu * r2
                + 4.f * mu2 * mu2 * mu;
    }
    {   // y-side, into S[5..9]
        float mu = S[5][c] * inv;
        float r2 = S[6][c] * inv, r3 = S[7][c] * inv, r4 = S[8][c] * inv, r5 = S[9][c] * inv;
        float mu2 = mu * mu;
        S[5][c] = mu;
        S[6][c] = r2 - mu2;
        S[7][c] = r3 - 3.f * mu * r2 + 2.f * mu2 * mu;
        S[8][c] = r4 - 4.f * mu * r3 + 6.f * mu2 * r2 - 3.f * mu2 * mu2;
        S[9][c] = r5 - 5.f * mu * r4 + 10.f * mu2 * r3 - 10.f * mu2 * mu * r2
                + 4.f * mu2 * mu2 * mu;
    }
    // squared diffs, reduced over channels (8 warps), one moment at a time
    float q[5];
#pragma unroll
    for (int k = 0; k < 5; k++) {
        float d = S[k][c] - S[k + 5][c];
        q[k] = warp_red(d * d);
    }
    __shared__ float shq[8][5];
    if (lane == 0) {
#pragma unroll
        for (int k = 0; k < 5; k++) shq[wid][k] = q[k];
    }
    __syncthreads();
    if (tid == 0) {
        float loss = 0.f;
#pragma unroll
        for (int k = 0; k < 5; k++) {
            float t = 0.f;
#pragma unroll
            for (int w = 0; w < 8; w++) t += shq[w][k];
            loss += sqrtf(t);
        }
        out[0] = loss;
        g_done = 0u;  // reset for next (graph-replayed) launch
    }
}

extern "C" void kernel_launch(void* const* d_in, const int* in_sizes, int n_in,
                              void* d_out, int out_size) {
    const float* x = (const float*)d_in[0];
    const float* t = (const float*)d_in[1];
    style_loss_kernel<<<SLABS, THREADS>>>(x, t, (float*)d_out);
}

// round 13
// speedup vs baseline: 1.0846x; 1.0150x over previous
#include <cuda_runtime.h>
#include <math.h>

// Shapes fixed: x, target = [B=8, C=256, H=128, W=128] fp32.
#define B_DIM   8
#define C_DIM   256
#define HW_DIM  (128 * 128)                 // 16384 floats per (b,c) slab
#define N_PER_C ((float)(B_DIM * HW_DIM))   // 131072 elements per channel
#define SLABS   (B_DIM * C_DIM)             // 2048 flat slabs, slab s = b*256 + c
#define THREADS 256
#define P2_ITER (HW_DIM / (THREADS * 4))    // 16 ulonglong2 loads (4 floats) per thread/tensor

// Per-slab partial sums, moment-major for coalesced finalize reads.
__device__ float g_part[10][SLABS];

typedef unsigned long long ull;

// Blackwell packed f32x2 ops (FMA pipe, 2 floats per instruction; PTX-only).
__device__ __forceinline__ ull mul2(ull a, ull b) {
    ull r; asm("mul.rn.f32x2 %0, %1, %2;" : "=l"(r) : "l"(a), "l"(b)); return r;
}
__device__ __forceinline__ ull add2(ull a, ull b) {
    ull r; asm("add.rn.f32x2 %0, %1, %2;" : "=l"(r) : "l"(a), "l"(b)); return r;
}
__device__ __forceinline__ ull fma2(ull a, ull b, ull c) {
    ull r; asm("fma.rn.f32x2 %0, %1, %2, %3;" : "=l"(r) : "l"(a), "l"(b), "l"(c)); return r;
}
__device__ __forceinline__ float unpack_sum(ull p) {
    unsigned int lo = (unsigned int)p, hi = (unsigned int)(p >> 32);
    return __uint_as_float(lo) + __uint_as_float(hi);
}

__device__ __forceinline__ float warp_red(float v) {
#pragma unroll
    for (int o = 16; o; o >>= 1) v += __shfl_xor_sync(0xffffffffu, v, o);
    return v;
}

__global__ __launch_bounds__(THREADS) void moments_kernel(
    const float* __restrict__ x, const float* __restrict__ y) {
    const int s = blockIdx.x;                       // contiguous 64KB slab
    const size_t base = (size_t)s * HW_DIM;
    const ulonglong2* __restrict__ x2 = (const ulonglong2*)(x + base);
    const ulonglong2* __restrict__ y2 = (const ulonglong2*)(y + base);
    const int tid = threadIdx.x;

    // f32x2 accumulators: each holds 2 reduction lanes.
    ull sx1 = 0, sx2 = 0, sx3 = 0, sx4 = 0, sx5 = 0;
    ull sy1 = 0, sy2 = 0, sy3 = 0, sy4 = 0, sy5 = 0;

#pragma unroll 4
    for (int i = 0; i < P2_ITER; i++) {
        ulonglong2 vx = __ldcs(&x2[tid + i * THREADS]);  // 4 floats, streamed
        ulonglong2 vy = __ldcs(&y2[tid + i * THREADS]);
#pragma unroll
        for (int l = 0; l < 2; l++) {
            ull p = (l == 0) ? vx.x : vx.y;
            ull p2 = mul2(p, p);
            ull p3 = mul2(p2, p);
            sx1 = add2(sx1, p);
            sx2 = add2(sx2, p2);
            sx3 = add2(sx3, p3);
            sx4 = fma2(p2, p2, sx4);
            sx5 = fma2(p3, p2, sx5);
            ull q = (l == 0) ? vy.x : vy.y;
            ull q2 = mul2(q, q);
            ull q3 = mul2(q2, q);
            sy1 = add2(sy1, q);
            sy2 = add2(sy2, q2);
            sy3 = add2(sy3, q3);
            sy4 = fma2(q2, q2, sy4);
            sy5 = fma2(q3, q2, sy5);
        }
    }

    // Collapse packed lanes, then fp32 warp tree-reduce.
    float a1 = warp_red(unpack_sum(sx1)), a2 = warp_red(unpack_sum(sx2));
    float a3 = warp_red(unpack_sum(sx3)), a4 = warp_red(unpack_sum(sx4));
    float a5 = warp_red(unpack_sum(sx5));
    float b1 = warp_red(unpack_sum(sy1)), b2 = warp_red(unpack_sum(sy2));
    float b3 = warp_red(unpack_sum(sy3)), b4 = warp_red(unpack_sum(sy4));
    float b5 = warp_red(unpack_sum(sy5));

    __shared__ float sh[THREADS / 32][10];
    const int lane = tid & 31, wid = tid >> 5;
    if (lane == 0) {
        sh[wid][0] = a1; sh[wid][1] = a2; sh[wid][2] = a3; sh[wid][3] = a4; sh[wid][4] = a5;
        sh[wid][5] = b1; sh[wid][6] = b2; sh[wid][7] = b3; sh[wid][8] = b4; sh[wid][9] = b5;
    }
    __syncthreads();
    if (tid < 10) {
        float a = 0.f;
#pragma unroll
        for (int w = 0; w < THREADS / 32; w++) a += sh[w][tid];
        g_part[tid][s] = a;
    }
}

// All-fp32 finalize (fp64 pipe on B300 is ~35x slower than FFMA — avoid).
__global__ __launch_bounds__(C_DIM) void finalize_kernel(float* __restrict__ out) {
    const int c = threadIdx.x;  // one thread per channel; lanes consecutive in c

    float s[10];
#pragma unroll
    for (int j = 0; j < 10; j++) s[j] = 0.f;
#pragma unroll
    for (int b = 0; b < B_DIM; b++) {
#pragma unroll
        for (int j = 0; j < 10; j++)
            s[j] += g_part[j][b * C_DIM + c];  // coalesced, L2-hot
    }
    const float inv = 1.0f / N_PER_C;
    float mux = s[0] * inv, r2x = s[1] * inv, r3x = s[2] * inv, r4x = s[3] * inv, r5x = s[4] * inv;
    float muy = s[5] * inv, r2y = s[6] * inv, r3y = s[7] * inv, r4y = s[8] * inv, r5y = s[9] * inv;

    float mux2 = mux * mux, muy2 = muy * muy;
    // exact binomial recovery of centered moments from raw moments
    float m2x = r2x - mux2;
    float m3x = r3x - 3.f * mux * r2x + 2.f * mux2 * mux;
    float m4x = r4x - 4.f * mux * r3x + 6.f * mux2 * r2x - 3.f * mux2 * mux2;
    float m5x = r5x - 5.f * mux * r4x + 10.f * mux2 * r3x - 10.f * mux2 * mux * r2x
              + 4.f * mux2 * mux2 * mux;
    float m2y = r2y - muy2;
    float m3y = r3y - 3.f * muy * r2y + 2.f * muy2 * muy;
    float m4y = r4y - 4.f * muy * r3y + 6.f * muy2 * r2y - 3.f * muy2 * muy2;
    float m5y = r5y - 5.f * muy * r4y + 10.f * muy2 * r3y - 10.f * muy2 * muy * r2y
              + 4.f * muy2 * muy2 * muy;

    float d1 = mux - muy, d2 = m2x - m2y, d3 = m3x - m3y, d4 = m4x - m4y, d5 = m5x - m5y;
    float q[5] = { d1 * d1, d2 * d2, d3 * d3, d4 * d4, d5 * d5 };

#pragma unroll
    for (int k = 0; k < 5; k++) {
#pragma unroll
        for (int o = 16; o; o >>= 1) q[k] += __shfl_xor_sync(0xffffffffu, q[k], o);
    }
    __shared__ float shq[8][5];
    const int lane = c & 31, wid = c >> 5;
    if (lane == 0) {
#pragma unroll
        for (int k = 0; k < 5; k++) shq[wid][k] = q[k];
    }
    __syncthreads();
    if (c == 0) {
        float tot[5] = {0, 0, 0, 0, 0};
#pragma unroll
        for (int w = 0; w < 8; w++)
#pragma unroll
            for (int k = 0; k < 5; k++) tot[k] += shq[w][k];
        out[0] = sqrtf(tot[0]) + sqrtf(tot[1]) + sqrtf(tot[2]) + sqrtf(tot[3]) + sqrtf(tot[4]);
    }
}

extern "C" void kernel_launch(void* const* d_in, const int* in_sizes, int n_in,
                              void* d_out, int out_size) {
    const float* x = (const float*)d_in[0];
    const float* t = (const float*)d_in[1];
    moments_kernel<<<SLABS, THREADS>>>(x, t);
    finalize_kernel<<<1, C_DIM>>>((float*)d_out);
}

// round 15
// speedup vs baseline: 1.1143x; 1.0274x over previous
#include <cuda_runtime.h>
#include <math.h>

// Shapes fixed: x, target = [B=8, C=256, H=128, W=128] fp32.
#define B_DIM   8
#define C_DIM   256
#define HW_DIM  (128 * 128)                 // 16384 floats per (b,c) slab
#define N_PER_C ((float)(B_DIM * HW_DIM))   // 131072 elements per channel
#define SLABS   (B_DIM * C_DIM)             // 2048 flat slabs, slab s = b*256 + c
#define THREADS 256
#define P2_ITER (HW_DIM / (THREADS * 4))    // 16 ulonglong2 loads (4 floats) per thread

// Per-slab partial sums, moment-major. x-CTAs fill rows 0..4, y-CTAs rows 5..9.
__device__ float g_part[10][SLABS];

typedef unsigned long long ull;

// Blackwell packed f32x2 ops (FMA pipe, 2 floats per instruction; PTX-only).
__device__ __forceinline__ ull mul2(ull a, ull b) {
    ull r; asm("mul.rn.f32x2 %0, %1, %2;" : "=l"(r) : "l"(a), "l"(b)); return r;
}
__device__ __forceinline__ ull add2(ull a, ull b) {
    ull r; asm("add.rn.f32x2 %0, %1, %2;" : "=l"(r) : "l"(a), "l"(b)); return r;
}
__device__ __forceinline__ ull fma2(ull a, ull b, ull c) {
    ull r; asm("fma.rn.f32x2 %0, %1, %2, %3;" : "=l"(r) : "l"(a), "l"(b), "l"(c)); return r;
}
__device__ __forceinline__ float unpack_sum(ull p) {
    unsigned int lo = (unsigned int)p, hi = (unsigned int)(p >> 32);
    return __uint_as_float(lo) + __uint_as_float(hi);
}

__device__ __forceinline__ float warp_red(float v) {
#pragma unroll
    for (int o = 16; o; o >>= 1) v += __shfl_xor_sync(0xffffffffu, v, o);
    return v;
}

// Split-tensor moments: each CTA reduces ONE tensor's slab -> only 5 packed
// accumulators (10 regs) live -> ~30 regs -> 8 CTAs/SM (64/64 warps) for
// deeper DRAM-latency coverage. Same total traffic/flops as the fused form.
__global__ __launch_bounds__(THREADS) void moments_kernel(
    const float* __restrict__ x, const float* __restrict__ y) {
    const int cid = blockIdx.x;
    const int is_y = (cid >= SLABS);
    const int s = is_y ? (cid - SLABS) : cid;
    const float* __restrict__ src = is_y ? y : x;
    const ulonglong2* __restrict__ p2 =
        (const ulonglong2*)(src + (size_t)s * HW_DIM);  // contiguous 64KB slab
    const int tid = threadIdx.x;

    ull s1 = 0, s2 = 0, s3 = 0, s4 = 0, s5 = 0;  // f32x2 accumulators

#pragma unroll 4
    for (int i = 0; i < P2_ITER; i++) {
        ulonglong2 v = __ldcs(&p2[tid + i * THREADS]);  // 4 floats, streamed
#pragma unroll
        for (int l = 0; l < 2; l++) {
            ull p  = (l == 0) ? v.x : v.y;
            ull pp = mul2(p, p);
            ull p3 = mul2(pp, p);
            s1 = add2(s1, p);
            s2 = add2(s2, pp);
            s3 = add2(s3, p3);
            s4 = fma2(pp, pp, s4);
            s5 = fma2(p3, pp, s5);
        }
    }

    float a1 = warp_red(unpack_sum(s1)), a2 = warp_red(unpack_sum(s2));
    float a3 = warp_red(unpack_sum(s3)), a4 = warp_red(unpack_sum(s4));
    float a5 = warp_red(unpack_sum(s5));

    __shared__ float sh[THREADS / 32][5];
    const int lane = tid & 31, wid = tid >> 5;
    if (lane == 0) {
        sh[wid][0] = a1; sh[wid][1] = a2; sh[wid][2] = a3;
        sh[wid][3] = a4; sh[wid][4] = a5;
    }
    __syncthreads();
    if (tid < 5) {
        float a = 0.f;
#pragma unroll
        for (int w = 0; w < THREADS / 32; w++) a += sh[w][tid];
        g_part[tid + (is_y ? 5 : 0)][s] = a;
    }
}

// All-fp32 finalize (fp64 pipe on B300 is ~35x slower than FFMA — avoid).
__global__ __launch_bounds__(C_DIM) void finalize_kernel(float* __restrict__ out) {
    const int c = threadIdx.x;  // one thread per channel; lanes consecutive in c

    float s[10];
#pragma unroll
    for (int j = 0; j < 10; j++) s[j] = 0.f;
#pragma unroll
    for (int b = 0; b < B_DIM; b++) {
#pragma unroll
        for (int j = 0; j < 10; j++)
            s[j] += g_part[j][b * C_DIM + c];  // coalesced, L2-hot
    }
    const float inv = 1.0f / N_PER_C;
    float mux = s[0] * inv, r2x = s[1] * inv, r3x = s[2] * inv, r4x = s[3] * inv, r5x = s[4] * inv;
    float muy = s[5] * inv, r2y = s[6] * inv, r3y = s[7] * inv, r4y = s[8] * inv, r5y = s[9] * inv;

    float mux2 = mux * mux, muy2 = muy * muy;
    // exact binomial recovery of centered moments from raw moments
    float m2x = r2x - mux2;
    float m3x = r3x - 3.f * mux * r2x + 2.f * mux2 * mux;
    float m4x = r4x - 4.f * mux * r3x + 6.f * mux2 * r2x - 3.f * mux2 * mux2;
    float m5x = r5x - 5.f * mux * r4x + 10.f * mux2 * r3x - 10.f * mux2 * mux * r2x
              + 4.f * mux2 * mux2 * mux;
    float m2y = r2y - muy2;
    float m3y = r3y - 3.f * muy * r2y + 2.f * muy2 * muy;
    float m4y = r4y - 4.f * muy * r3y + 6.f * muy2 * r2y - 3.f * muy2 * muy2;
    float m5y = r5y - 5.f * muy * r4y + 10.f * muy2 * r3y - 10.f * muy2 * muy * r2y
              + 4.f * muy2 * muy2 * muy;

    float d1 = mux - muy, d2 = m2x - m2y, d3 = m3x - m3y, d4 = m4x - m4y, d5 = m5x - m5y;
    float q[5] = { d1 * d1, d2 * d2, d3 * d3, d4 * d4, d5 * d5 };

#pragma unroll
    for (int k = 0; k < 5; k++) {
#pragma unroll
        for (int o = 16; o; o >>= 1) q[k] += __shfl_xor_sync(0xffffffffu, q[k], o);
    }
    __shared__ float shq[8][5];
    const int lane = c & 31, wid = c >> 5;
    if (lane == 0) {
#pragma unroll
        for (int k = 0; k < 5; k++) shq[wid][k] = q[k];
    }
    __syncthreads();
    if (c == 0) {
        float tot[5] = {0, 0, 0, 0, 0};
#pragma unroll
        for (int w = 0; w < 8; w++)
#pragma unroll
            for (int k = 0; k < 5; k++) tot[k] += shq[w][k];
        out[0] = sqrtf(tot[0]) + sqrtf(tot[1]) + sqrtf(tot[2]) + sqrtf(tot[3]) + sqrtf(tot[4]);
    }
}

extern "C" void kernel_launch(void* const* d_in, const int* in_sizes, int n_in,
                              void* d_out, int out_size) {
    const float* x = (const float*)d_in[0];
    const float* t = (const float*)d_in[1];
    moments_kernel<<<2 * SLABS, THREADS>>>(x, t);
    finalize_kernel<<<1, C_DIM>>>((float*)d_out);
}